// round 7
// baseline (speedup 1.0000x reference)
#include <cuda_runtime.h>
#include <cuda_fp16.h>
#include <cstdint>

// Problem constants
#define BB   16
#define CC   384      // C
#define CO   1536     // EXP*C
#define HW   1024     // 32*32
#define EMB_ 1024
#define NG   32
#define CPG  12
#define EPS_ 1e-5f

// ---------------- scratch (device globals) ---------------------------------
__device__ __align__(16) float  g_A[BB * CC];
__device__ __align__(16) float  g_D[BB * CC];
__device__ __align__(16) float  g_S[BB * CO];
__device__ __align__(16) float  g_T[BB * CO];
__device__ __align__(16) __half g_W1h[CO * CC];                // fp16 w1 [o][c]
__device__ __align__(16) __half g_W2h[CC * CO];                // fp16 w2 [o2][c']
__device__ __align__(16) __half g_Xnh[(size_t)BB * HW * CC];   // fp16 xn^T [b][s][c]
__device__ __align__(16) __half g_Hh[(size_t)BB * HW * CO];    // fp16 hidden [b][s][o]

// ---------------- helpers --------------------------------------------------
__device__ __forceinline__ void cpa16(uint32_t dst, const void* src) {
    asm volatile("cp.async.cg.shared.global [%0], [%1], 16;" :: "r"(dst), "l"(src));
}
#define CP_COMMIT() asm volatile("cp.async.commit_group;")
#define CP_WAIT2()  asm volatile("cp.async.wait_group 2;")

#define LDSM4(r0, r1, r2, r3, a)                                               \
    asm volatile("ldmatrix.sync.aligned.m8n8.x4.shared.b16 {%0,%1,%2,%3}, [%4];" \
        : "=r"(r0), "=r"(r1), "=r"(r2), "=r"(r3) : "r"(a))

#define MMA_F16(d, a, b)                                                       \
    asm volatile(                                                              \
        "mma.sync.aligned.m16n8k16.row.col.f32.f16.f16.f32 "                   \
        "{%0,%1,%2,%3},{%4,%5,%6,%7},{%8,%9},{%0,%1,%2,%3};\n"                 \
        : "+f"((d)[0]), "+f"((d)[1]), "+f"((d)[2]), "+f"((d)[3])               \
        : "r"((a)[0]), "r"((a)[1]), "r"((a)[2]), "r"((a)[3]),                  \
          "r"((b)[0]), "r"((b)[1]))

// ---------------------------------------------------------------------------
// K1: GroupNorm stats -> per-channel affine (A, D)
// ---------------------------------------------------------------------------
__global__ void k_gnstats(const float* __restrict__ x,
                          const float* __restrict__ gnw,
                          const float* __restrict__ gnb) {
    int bg = blockIdx.x;
    int b = bg >> 5;
    int gi = bg & 31;
    const float4* p = (const float4*)(x + ((size_t)b * CC + (size_t)gi * CPG) * HW);
    float s = 0.f, ss = 0.f;
#pragma unroll
    for (int i = 0; i < 12; i++) {
        float4 v = p[threadIdx.x + i * 256];
        s  += v.x + v.y + v.z + v.w;
        ss += v.x * v.x + v.y * v.y + v.z * v.z + v.w * v.w;
    }
#pragma unroll
    for (int off = 16; off; off >>= 1) {
        s  += __shfl_xor_sync(0xffffffffu, s, off);
        ss += __shfl_xor_sync(0xffffffffu, ss, off);
    }
    __shared__ float sh[64];
    int w = threadIdx.x >> 5, l = threadIdx.x & 31;
    if (l == 0) { sh[w] = s; sh[32 + w] = ss; }
    __syncthreads();
    if (threadIdx.x < CPG) {
        float S = 0.f, SS = 0.f;
#pragma unroll
        for (int i = 0; i < 8; i++) { S += sh[i]; SS += sh[32 + i]; }
        float mean = S * (1.0f / 12288.0f);
        float var  = SS * (1.0f / 12288.0f) - mean * mean;
        float rstd = rsqrtf(var + EPS_);
        int cch = gi * CPG + threadIdx.x;
        float wv = gnw[cch], bv = gnb[cch];
        g_A[b * CC + cch] = rstd * wv;
        g_D[b * CC + cch] = bv - mean * rstd * wv;
    }
}

// ---------------------------------------------------------------------------
// K2: emb_out = emb @ we.T + be. One warp per output row o (0..3071),
// weight row in registers, loop over all 16 batches (emb is L1-resident).
// ---------------------------------------------------------------------------
__global__ void k_emb(const float* __restrict__ emb,
                      const float* __restrict__ we,
                      const float* __restrict__ be) {
    int o = blockIdx.x * 8 + (threadIdx.x >> 5);   // 0..3071
    int lane = threadIdx.x & 31;
    const float4* w4 = (const float4*)(we + (size_t)o * EMB_);
    float4 wv[8];
#pragma unroll
    for (int i = 0; i < 8; i++) wv[i] = w4[lane + i * 32];
    float bev = be[o];

    float mine = 0.f;
#pragma unroll
    for (int b = 0; b < BB; b++) {
        const float4* e4 = (const float4*)(emb + (size_t)b * EMB_);
        float s = 0.f;
#pragma unroll
        for (int i = 0; i < 8; i++) {
            float4 ev = e4[lane + i * 32];
            s += ev.x * wv[i].x + ev.y * wv[i].y + ev.z * wv[i].z + ev.w * wv[i].w;
        }
#pragma unroll
        for (int off = 16; off; off >>= 1)
            s += __shfl_xor_sync(0xffffffffu, s, off);
        if (lane == b) mine = s;
    }
    if (lane < BB) {
        if (o < CO) g_S[lane * CO + o] = 1.0f + mine + bev;
        else        g_T[lane * CO + (o - CO)] = mine + bev;
    }
}

// ---------------------------------------------------------------------------
// K3: weights -> fp16
// ---------------------------------------------------------------------------
__global__ void k_prep(const float* __restrict__ w1,
                       const float* __restrict__ w2) {
    const int N1 = CO * CC / 4;
    int t = blockIdx.x * blockDim.x + threadIdx.x;
    const float4* src = (t < N1) ? (const float4*)w1 : (const float4*)w2;
    int i = (t < N1) ? t : t - N1;
    float4 v = src[i];
    __half2 lo = __floats2half2_rn(v.x, v.y);
    __half2 hi = __floats2half2_rn(v.z, v.w);
    uint2 pk = make_uint2(*(uint32_t*)&lo, *(uint32_t*)&hi);
    if (t < N1) ((uint2*)g_W1h)[i] = pk;
    else        ((uint2*)g_W2h)[i] = pk;
}

// ---------------------------------------------------------------------------
// K4: xn^T = fp16(A*x + D), transposed to [b][s][c]  (64x64 smem tiles)
// ---------------------------------------------------------------------------
__global__ void k_norm_t(const float* __restrict__ x) {
    __shared__ float sm[64][65];
    int b = blockIdx.z;
    int cg = blockIdx.y * 64;
    int sg = blockIdx.x * 64;
    int tid = threadIdx.x;
    int r = tid >> 2, q = tid & 3;
    float a = g_A[b * CC + cg + r];
    float d = g_D[b * CC + cg + r];
    const float* xr = x + ((size_t)b * CC + cg + r) * HW + sg + q * 16;
#pragma unroll
    for (int i = 0; i < 4; i++) {
        float4 v = *(const float4*)(xr + i * 4);
        sm[r][q * 16 + i * 4 + 0] = fmaf(a, v.x, d);
        sm[r][q * 16 + i * 4 + 1] = fmaf(a, v.y, d);
        sm[r][q * 16 + i * 4 + 2] = fmaf(a, v.z, d);
        sm[r][q * 16 + i * 4 + 3] = fmaf(a, v.w, d);
    }
    __syncthreads();
    __half* orow = g_Xnh + ((size_t)b * HW + sg + r) * CC + cg + q * 16;
#pragma unroll
    for (int i = 0; i < 4; i++) {
        __half2 lo = __floats2half2_rn(sm[q*16+i*4+0][r], sm[q*16+i*4+1][r]);
        __half2 hi = __floats2half2_rn(sm[q*16+i*4+2][r], sm[q*16+i*4+3][r]);
        *(uint2*)(orow + i * 4) = make_uint2(*(uint32_t*)&lo, *(uint32_t*)&hi);
    }
}

// ---------------------------------------------------------------------------
// GEMM core (templated): CTA tile 128(M) x (BROWS)(N), BK=32 fp16, 4 stages.
// Row pitch 80B (ldmatrix phase-conflict-free). One __syncthreads per k-tile,
// CORRECT multistage order: wait_group -> __syncthreads -> fill -> commit ->
// compute. (Barrier AFTER the wait gives cross-thread cp.async visibility;
// the same barrier protects the WAR on the fill target.)
// ---------------------------------------------------------------------------
#define ROWPITCH 80
#define TILE_A   (128 * ROWPITCH)

extern __shared__ uint8_t dsm8[];

template <int BROWS>
__device__ __forceinline__ void fill_stage(uint32_t sdst,
        const __half* Asrc, size_t lda, const __half* Bsrc, size_t ldb, int tid) {
    constexpr int TOT = (512 + BROWS * 4);
#pragma unroll
    for (int i = 0; i < TOT / 256; i++) {
        int ch = tid + i * 256;
        bool isB = ch >= 512;
        int base = isB ? (ch - 512) : ch;
        int r = base >> 2, cb = base & 3;
        const __half* src = isB ? (Bsrc + (size_t)r * ldb + cb * 8)
                                : (Asrc + (size_t)r * lda + cb * 8);
        cpa16(sdst + (isB ? TILE_A : 0) + r * ROWPITCH + cb * 16, src);
    }
}

template <int KT, int BROWS, int NT>
__device__ __forceinline__ void gemm_mainloop(
        const __half* Abase, size_t lda, const __half* Bbase, size_t ldb,
        float (&acc)[2][NT][4], int tid) {
    constexpr int STG = TILE_A + BROWS * ROWPITCH;
    const int lane = tid & 31, warp = tid >> 5;
    const int wm = warp & 3, wn = warp >> 2;
#pragma unroll
    for (int i = 0; i < 2; i++)
#pragma unroll
        for (int j = 0; j < NT; j++)
#pragma unroll
            for (int e = 0; e < 4; e++) acc[i][j][e] = 0.f;

    uint32_t smb = (uint32_t)__cvta_generic_to_shared(dsm8);
    uint32_t aoff = (uint32_t)((wm * 32 + (lane & 15)) * ROWPITCH + (lane >> 4) * 16);
    uint32_t boff = (uint32_t)((wn * (NT * 8) + (lane & 7) + ((lane >> 4) << 3)) * ROWPITCH
                               + ((lane >> 3) & 1) * 16);

    // prologue: stages 0..2, one commit each (commits #1..#3)
#pragma unroll
    for (int s = 0; s < 3; s++) {
        fill_stage<BROWS>(smb + s * STG, Abase + s * 32, lda, Bbase + s * 32, ldb, tid);
        CP_COMMIT();
    }

    for (int kt = 0; kt < KT; kt++) {
        // commits before this wait: 3 + kt. wait_group 2 => completed >= kt+1,
        // i.e. the fill of stage kt has landed (for THIS thread).
        CP_WAIT2();
        __syncthreads();   // now stage kt is visible to ALL threads

        if (kt + 3 < KT)
            fill_stage<BROWS>(smb + ((kt + 3) & 3) * STG,
                              Abase + (size_t)(kt + 3) * 32, lda,
                              Bbase + (size_t)(kt + 3) * 32, ldb, tid);
        CP_COMMIT();       // commit every iteration (empty ok) keeps count exact

        uint32_t sA = smb + (kt & 3) * STG;
        uint32_t sB = sA + TILE_A;
#pragma unroll
        for (int kk = 0; kk < 2; kk++) {
            uint32_t af[2][4], bf[NT][2];
#pragma unroll
            for (int mt = 0; mt < 2; mt++)
                LDSM4(af[mt][0], af[mt][1], af[mt][2], af[mt][3],
                      sA + aoff + mt * 16 * ROWPITCH + kk * 32);
#pragma unroll
            for (int p = 0; p < NT / 2; p++) {
                uint32_t r0, r1, r2, r3;
                LDSM4(r0, r1, r2, r3, sB + boff + p * 16 * ROWPITCH + kk * 32);
                bf[2 * p][0] = r0;  bf[2 * p][1] = r1;
                bf[2 * p + 1][0] = r2; bf[2 * p + 1][1] = r3;
            }
#pragma unroll
            for (int mt = 0; mt < 2; mt++)
#pragma unroll
                for (int nt = 0; nt < NT; nt++)
                    MMA_F16(acc[mt][nt], af[mt], bf[nt]);
        }
    }
}

#define SMEM1_BYTES (4 * (TILE_A + 128 * ROWPITCH))   // 81920
#define SMEM2_BYTES (4 * (TILE_A + 64 * ROWPITCH))    // 61440

// ---------------------------------------------------------------------------
// K5: GEMM1: D[s,o]; M=s(128), N=o(128), K=CC.
// epilogue: +b1, silu, *(1+scale)+shift -> H[b][s][o] fp16
// ---------------------------------------------------------------------------
__global__ void __launch_bounds__(256, 2)
k_gemm1(const float* __restrict__ b1) {
    __shared__ float sb1[128], sS[128], sT[128];
    const int tid = threadIdx.x;
    const int b = blockIdx.z;
    const int o0 = blockIdx.y * 128;
    const int s0 = blockIdx.x * 128;
    if (tid < 128) {
        int o = o0 + tid;
        sb1[tid] = b1[o];
        sS[tid]  = g_S[b * CO + o];
        sT[tid]  = g_T[b * CO + o];
    }
    __syncthreads();

    const __half* Abase = g_Xnh + ((size_t)b * HW + s0) * CC;
    const __half* Bbase = g_W1h + (size_t)o0 * CC;
    float acc[2][8][4];
    gemm_mainloop<CC / 32, 128, 8>(Abase, CC, Bbase, CC, acc, tid);

    const int lane = tid & 31, warp = tid >> 5;
    const int wm = warp & 3, wn = warp >> 2;
    const int g = lane >> 2, t = lane & 3;
    __half* Hb = g_Hh + ((size_t)b * HW + s0) * CO + o0;
#pragma unroll
    for (int mt = 0; mt < 2; mt++)
#pragma unroll
        for (int h = 0; h < 2; h++) {
            int s_loc = wm * 32 + mt * 16 + h * 8 + g;
            __half* Hrow = Hb + (size_t)s_loc * CO;
#pragma unroll
            for (int nt = 0; nt < 8; nt++) {
                int oc = wn * 64 + nt * 8 + t * 2;
                float v0 = acc[mt][nt][h * 2 + 0] + sb1[oc];
                float v1 = acc[mt][nt][h * 2 + 1] + sb1[oc + 1];
                float h0 = v0 / (1.0f + __expf(-v0));
                float h1 = v1 / (1.0f + __expf(-v1));
                __half2 pk = __floats2half2_rn(h0 * sS[oc] + sT[oc],
                                               h1 * sS[oc + 1] + sT[oc + 1]);
                *(uint32_t*)(Hrow + oc) = *(uint32_t*)&pk;
            }
        }
}

// ---------------------------------------------------------------------------
// K6: GEMM2: D[o2,s]; M=o2(128), N=s(64), K=CO. Grid 16x3x16 = 768 CTAs.
// epilogue: +b2 + residual x -> out[b][o2][s] (float2 coalesced)
// ---------------------------------------------------------------------------
__global__ void __launch_bounds__(256, 2)
k_gemm2(const float* __restrict__ b2,
        const float* __restrict__ x,
        float* __restrict__ out) {
    __shared__ float sb2[128];
    const int tid = threadIdx.x;
    const int b = blockIdx.z;
    const int o20 = blockIdx.y * 128;
    const int s0 = blockIdx.x * 64;
    if (tid < 128) sb2[tid] = b2[o20 + tid];
    __syncthreads();

    const __half* Abase = g_W2h + (size_t)o20 * CO;
    const __half* Bbase = g_Hh + ((size_t)b * HW + s0) * CO;
    float acc[2][4][4];
    gemm_mainloop<CO / 32, 64, 4>(Abase, CO, Bbase, CO, acc, tid);

    const int lane = tid & 31, warp = tid >> 5;
    const int wm = warp & 3, wn = warp >> 2;
    const int g = lane >> 2, t = lane & 3;
#pragma unroll
    for (int mt = 0; mt < 2; mt++)
#pragma unroll
        for (int h = 0; h < 2; h++) {
            int mloc = wm * 32 + mt * 16 + h * 8 + g;
            int o2 = o20 + mloc;
            float bv = sb2[mloc];
            const float* xrow = x + (size_t)b * CC * HW + (size_t)o2 * HW + s0;
            float* orow = out + (size_t)b * CC * HW + (size_t)o2 * HW + s0;
#pragma unroll
            for (int nt = 0; nt < 4; nt++) {
                int sc = wn * 32 + nt * 8 + t * 2;
                float2 xr = *(const float2*)(xrow + sc);
                float2 ov;
                ov.x = acc[mt][nt][h * 2 + 0] + bv + xr.x;
                ov.y = acc[mt][nt][h * 2 + 1] + bv + xr.y;
                *(float2*)(orow + sc) = ov;
            }
        }
}

// ---------------------------------------------------------------------------
extern "C" void kernel_launch(void* const* d_in, const int* in_sizes, int n_in,
                              void* d_out, int out_size) {
    const float* x    = (const float*)d_in[0];
    const float* emb  = (const float*)d_in[1];
    const float* gn_w = (const float*)d_in[2];
    const float* gn_b = (const float*)d_in[3];
    const float* w1   = (const float*)d_in[4];
    const float* b1   = (const float*)d_in[5];
    const float* we   = (const float*)d_in[6];
    const float* be   = (const float*)d_in[7];
    const float* w2   = (const float*)d_in[8];
    const float* b2   = (const float*)d_in[9];
    float* out = (float*)d_out;

    static bool attr_set = false;
    if (!attr_set) {
        cudaFuncSetAttribute(k_gemm1, cudaFuncAttributeMaxDynamicSharedMemorySize, SMEM1_BYTES);
        cudaFuncSetAttribute(k_gemm2, cudaFuncAttributeMaxDynamicSharedMemorySize, SMEM2_BYTES);
        attr_set = true;
    }

    k_gnstats<<<BB * NG, 256>>>(x, gn_w, gn_b);
    k_emb<<<(2 * CO) / 8, 256>>>(emb, we, be);
    k_prep<<<(2 * CO * CC / 4) / 256, 256>>>(w1, w2);
    k_norm_t<<<dim3(HW / 64, CC / 64, BB), 256>>>(x);
    k_gemm1<<<dim3(HW / 128, CO / 128, BB), 256, SMEM1_BYTES>>>(b1);
    k_gemm2<<<dim3(HW / 64, CC / 128, BB), 256, SMEM2_BYTES>>>(b2, x, out);
}

// round 8
// speedup vs baseline: 1.0364x; 1.0364x over previous
#include <cuda_runtime.h>
#include <cuda_fp16.h>
#include <cstdint>

// Problem constants
#define BB   16
#define CC   384      // C
#define CO   1536     // EXP*C
#define HW   1024     // 32*32
#define EMB_ 1024
#define NG   32
#define CPG  12
#define EPS_ 1e-5f

// ---------------- scratch (device globals) ---------------------------------
__device__ __align__(16) float  g_A[BB * CC];
__device__ __align__(16) float  g_D[BB * CC];
__device__ __align__(16) float  g_S[BB * CO];
__device__ __align__(16) float  g_T[BB * CO];
__device__ __align__(16) __half g_W1h[CO * CC];                // fp16 w1 [o][c]
__device__ __align__(16) __half g_W2h[CC * CO];                // fp16 w2 [o2][c']
__device__ __align__(16) __half g_Xnh[(size_t)BB * HW * CC];   // fp16 xn^T [b][s][c]
__device__ __align__(16) __half g_Hh[(size_t)BB * HW * CO];    // fp16 hidden [b][s][o]

// ---------------- helpers --------------------------------------------------
__device__ __forceinline__ void cpa16(uint32_t dst, const void* src) {
    asm volatile("cp.async.cg.shared.global [%0], [%1], 16;" :: "r"(dst), "l"(src));
}
#define CP_COMMIT() asm volatile("cp.async.commit_group;")
#define CP_WAIT3()  asm volatile("cp.async.wait_group 3;")

#define LDSM4(r0, r1, r2, r3, a)                                               \
    asm volatile("ldmatrix.sync.aligned.m8n8.x4.shared.b16 {%0,%1,%2,%3}, [%4];" \
        : "=r"(r0), "=r"(r1), "=r"(r2), "=r"(r3) : "r"(a))

#define MMA_F16(d, a, b)                                                       \
    asm volatile(                                                              \
        "mma.sync.aligned.m16n8k16.row.col.f32.f16.f16.f32 "                   \
        "{%0,%1,%2,%3},{%4,%5,%6,%7},{%8,%9},{%0,%1,%2,%3};\n"                 \
        : "+f"((d)[0]), "+f"((d)[1]), "+f"((d)[2]), "+f"((d)[3])               \
        : "r"((a)[0]), "r"((a)[1]), "r"((a)[2]), "r"((a)[3]),                  \
          "r"((b)[0]), "r"((b)[1]))

// ---------------------------------------------------------------------------
// K1: GroupNorm stats -> per-channel affine (A, D)
// ---------------------------------------------------------------------------
__global__ void k_gnstats(const float* __restrict__ x,
                          const float* __restrict__ gnw,
                          const float* __restrict__ gnb) {
    int bg = blockIdx.x;
    int b = bg >> 5;
    int gi = bg & 31;
    const float4* p = (const float4*)(x + ((size_t)b * CC + (size_t)gi * CPG) * HW);
    float s = 0.f, ss = 0.f;
#pragma unroll
    for (int i = 0; i < 12; i++) {
        float4 v = p[threadIdx.x + i * 256];
        s  += v.x + v.y + v.z + v.w;
        ss += v.x * v.x + v.y * v.y + v.z * v.z + v.w * v.w;
    }
#pragma unroll
    for (int off = 16; off; off >>= 1) {
        s  += __shfl_xor_sync(0xffffffffu, s, off);
        ss += __shfl_xor_sync(0xffffffffu, ss, off);
    }
    __shared__ float sh[64];
    int w = threadIdx.x >> 5, l = threadIdx.x & 31;
    if (l == 0) { sh[w] = s; sh[32 + w] = ss; }
    __syncthreads();
    if (threadIdx.x < CPG) {
        float S = 0.f, SS = 0.f;
#pragma unroll
        for (int i = 0; i < 8; i++) { S += sh[i]; SS += sh[32 + i]; }
        float mean = S * (1.0f / 12288.0f);
        float var  = SS * (1.0f / 12288.0f) - mean * mean;
        float rstd = rsqrtf(var + EPS_);
        int cch = gi * CPG + threadIdx.x;
        float wv = gnw[cch], bv = gnb[cch];
        g_A[b * CC + cch] = rstd * wv;
        g_D[b * CC + cch] = bv - mean * rstd * wv;
    }
}

// ---------------------------------------------------------------------------
// K2: emb_out = emb @ we.T + be. One warp per output row o, weight row in
// registers, loop over all 16 batches (emb is L1-resident). (R7 win: kept.)
// ---------------------------------------------------------------------------
__global__ void k_emb(const float* __restrict__ emb,
                      const float* __restrict__ we,
                      const float* __restrict__ be) {
    int o = blockIdx.x * 8 + (threadIdx.x >> 5);   // 0..3071
    int lane = threadIdx.x & 31;
    const float4* w4 = (const float4*)(we + (size_t)o * EMB_);
    float4 wv[8];
#pragma unroll
    for (int i = 0; i < 8; i++) wv[i] = w4[lane + i * 32];
    float bev = be[o];

    float mine = 0.f;
#pragma unroll
    for (int b = 0; b < BB; b++) {
        const float4* e4 = (const float4*)(emb + (size_t)b * EMB_);
        float s = 0.f;
#pragma unroll
        for (int i = 0; i < 8; i++) {
            float4 ev = e4[lane + i * 32];
            s += ev.x * wv[i].x + ev.y * wv[i].y + ev.z * wv[i].z + ev.w * wv[i].w;
        }
#pragma unroll
        for (int off = 16; off; off >>= 1)
            s += __shfl_xor_sync(0xffffffffu, s, off);
        if (lane == b) mine = s;
    }
    if (lane < BB) {
        if (o < CO) g_S[lane * CO + o] = 1.0f + mine + bev;
        else        g_T[lane * CO + (o - CO)] = mine + bev;
    }
}

// ---------------------------------------------------------------------------
// K3: weights -> fp16
// ---------------------------------------------------------------------------
__global__ void k_prep(const float* __restrict__ w1,
                       const float* __restrict__ w2) {
    const int N1 = CO * CC / 4;
    int t = blockIdx.x * blockDim.x + threadIdx.x;
    const float4* src = (t < N1) ? (const float4*)w1 : (const float4*)w2;
    int i = (t < N1) ? t : t - N1;
    float4 v = src[i];
    __half2 lo = __floats2half2_rn(v.x, v.y);
    __half2 hi = __floats2half2_rn(v.z, v.w);
    uint2 pk = make_uint2(*(uint32_t*)&lo, *(uint32_t*)&hi);
    if (t < N1) ((uint2*)g_W1h)[i] = pk;
    else        ((uint2*)g_W2h)[i] = pk;
}

// ---------------------------------------------------------------------------
// K4: xn^T = fp16(A*x + D), transposed to [b][s][c]  (64x64 smem tiles)
// ---------------------------------------------------------------------------
__global__ void k_norm_t(const float* __restrict__ x) {
    __shared__ float sm[64][65];
    int b = blockIdx.z;
    int cg = blockIdx.y * 64;
    int sg = blockIdx.x * 64;
    int tid = threadIdx.x;
    int r = tid >> 2, q = tid & 3;
    float a = g_A[b * CC + cg + r];
    float d = g_D[b * CC + cg + r];
    const float* xr = x + ((size_t)b * CC + cg + r) * HW + sg + q * 16;
#pragma unroll
    for (int i = 0; i < 4; i++) {
        float4 v = *(const float4*)(xr + i * 4);
        sm[r][q * 16 + i * 4 + 0] = fmaf(a, v.x, d);
        sm[r][q * 16 + i * 4 + 1] = fmaf(a, v.y, d);
        sm[r][q * 16 + i * 4 + 2] = fmaf(a, v.z, d);
        sm[r][q * 16 + i * 4 + 3] = fmaf(a, v.w, d);
    }
    __syncthreads();
    __half* orow = g_Xnh + ((size_t)b * HW + sg + r) * CC + cg + q * 16;
#pragma unroll
    for (int i = 0; i < 4; i++) {
        __half2 lo = __floats2half2_rn(sm[q*16+i*4+0][r], sm[q*16+i*4+1][r]);
        __half2 hi = __floats2half2_rn(sm[q*16+i*4+2][r], sm[q*16+i*4+3][r]);
        *(uint2*)(orow + i * 4) = make_uint2(*(uint32_t*)&lo, *(uint32_t*)&hi);
    }
}

// ---------------------------------------------------------------------------
// GEMM core: CTA tile 128x128, BK=32 fp16, 4-stage cp.async (R5 structure:
// fill -> commit -> wait_group 3 -> sync -> compute, depth-3 pipeline), plus
// a trailing sync to close the WAR window (next iter's fill targets the
// stage just computed; all warps must finish reading it first).
// ---------------------------------------------------------------------------
#define ROWPITCH 80
#define TILE_B   (128 * ROWPITCH)      // 10240 B per operand tile
#define STG_B    (2 * TILE_B)          // 20480 B per stage
#define SMEM_BYTES (4 * STG_B)         // 81920 B

extern __shared__ uint8_t dsm8[];

__device__ __forceinline__ void fill_stage(uint32_t sdst,
        const __half* Asrc, size_t lda, const __half* Bsrc, size_t ldb, int tid) {
#pragma unroll
    for (int i = 0; i < 4; i++) {
        int ch = tid + i * 256;            // 0..1023
        int isB = ch >> 9;                 // 512 chunks per operand
        int r   = (ch & 511) >> 2;
        int cb  = ch & 3;
        const __half* src = isB ? (Bsrc + (size_t)r * ldb + cb * 8)
                                : (Asrc + (size_t)r * lda + cb * 8);
        cpa16(sdst + isB * TILE_B + r * ROWPITCH + cb * 16, src);
    }
}

template <int KT>
__device__ __forceinline__ void gemm_mainloop(
        const __half* Abase, size_t lda, const __half* Bbase, size_t ldb,
        float acc[2][8][4], int tid) {
    const int lane = tid & 31, warp = tid >> 5;
    const int wm = warp & 3, wn = warp >> 2;
#pragma unroll
    for (int i = 0; i < 2; i++)
#pragma unroll
        for (int j = 0; j < 8; j++)
#pragma unroll
            for (int e = 0; e < 4; e++) acc[i][j][e] = 0.f;

    uint32_t smb = (uint32_t)__cvta_generic_to_shared(dsm8);
    uint32_t aoff = (uint32_t)((wm * 32 + (lane & 15)) * ROWPITCH + (lane >> 4) * 16);
    uint32_t boff = (uint32_t)((wn * 64 + (lane & 7) + ((lane >> 4) << 3)) * ROWPITCH
                               + ((lane >> 3) & 1) * 16);

    // prologue: stages 0..2
#pragma unroll
    for (int s = 0; s < 3; s++) {
        fill_stage(smb + s * STG_B, Abase + s * 32, lda, Bbase + s * 32, ldb, tid);
        CP_COMMIT();
    }

    for (int kt = 0; kt < KT; kt++) {
        if (kt + 3 < KT)
            fill_stage(smb + ((kt + 3) & 3) * STG_B,
                       Abase + (size_t)(kt + 3) * 32, lda,
                       Bbase + (size_t)(kt + 3) * 32, ldb, tid);
        CP_COMMIT();
        CP_WAIT3();        // this thread's stage-kt fill is done; 3 in flight
        __syncthreads();   // all threads' stage-kt fills visible

        uint32_t sA = smb + (kt & 3) * STG_B;
        uint32_t sB = sA + TILE_B;
#pragma unroll
        for (int kk = 0; kk < 2; kk++) {           // two k16 chunks
            uint32_t af[2][4], bf[8][2];
#pragma unroll
            for (int mt = 0; mt < 2; mt++)
                LDSM4(af[mt][0], af[mt][1], af[mt][2], af[mt][3],
                      sA + aoff + mt * 16 * ROWPITCH + kk * 32);
#pragma unroll
            for (int p = 0; p < 4; p++) {
                uint32_t r0, r1, r2, r3;
                LDSM4(r0, r1, r2, r3, sB + boff + p * 16 * ROWPITCH + kk * 32);
                bf[2 * p][0] = r0;  bf[2 * p][1] = r1;
                bf[2 * p + 1][0] = r2; bf[2 * p + 1][1] = r3;
            }
#pragma unroll
            for (int mt = 0; mt < 2; mt++)
#pragma unroll
                for (int nt = 0; nt < 8; nt++)
                    MMA_F16(acc[mt][nt], af[mt], bf[nt]);
        }
        __syncthreads();   // WAR guard: next iter's fill overwrites this stage
    }
}

// ---------------------------------------------------------------------------
// K5: GEMM1: D[s,o] = xn^T[s,c] @ w1[o,c]^T; M=s,N=o,K=CC.
// epilogue: +b1, silu, *(1+scale)+shift -> H[b][s][o] fp16
// ---------------------------------------------------------------------------
__global__ void __launch_bounds__(256, 2)
k_gemm1(const float* __restrict__ b1) {
    __shared__ float sb1[128], sS[128], sT[128];
    const int tid = threadIdx.x;
    const int b = blockIdx.z;
    const int o0 = blockIdx.y * 128;
    const int s0 = blockIdx.x * 128;
    if (tid < 128) {
        int o = o0 + tid;
        sb1[tid] = b1[o];
        sS[tid]  = g_S[b * CO + o];
        sT[tid]  = g_T[b * CO + o];
    }
    __syncthreads();

    const __half* Abase = g_Xnh + ((size_t)b * HW + s0) * CC;
    const __half* Bbase = g_W1h + (size_t)o0 * CC;
    float acc[2][8][4];
    gemm_mainloop<CC / 32>(Abase, CC, Bbase, CC, acc, tid);

    const int lane = tid & 31, warp = tid >> 5;
    const int wm = warp & 3, wn = warp >> 2;
    const int g = lane >> 2, t = lane & 3;
    __half* Hb = g_Hh + ((size_t)b * HW + s0) * CO + o0;
#pragma unroll
    for (int mt = 0; mt < 2; mt++)
#pragma unroll
        for (int h = 0; h < 2; h++) {
            int s_loc = wm * 32 + mt * 16 + h * 8 + g;
            __half* Hrow = Hb + (size_t)s_loc * CO;
#pragma unroll
            for (int nt = 0; nt < 8; nt++) {
                int oc = wn * 64 + nt * 8 + t * 2;
                float v0 = acc[mt][nt][h * 2 + 0] + sb1[oc];
                float v1 = acc[mt][nt][h * 2 + 1] + sb1[oc + 1];
                float h0 = v0 / (1.0f + __expf(-v0));
                float h1 = v1 / (1.0f + __expf(-v1));
                __half2 pk = __floats2half2_rn(h0 * sS[oc] + sT[oc],
                                               h1 * sS[oc + 1] + sT[oc + 1]);
                *(uint32_t*)(Hrow + oc) = *(uint32_t*)&pk;
            }
        }
}

// ---------------------------------------------------------------------------
// K6: GEMM2: D[o2,s] = w2[o2,c'] @ H[s,c']^T; M=o2,N=s,K=CO. (R5 tiling.)
// epilogue: +b2 + residual x -> out[b][o2][s] (float2 coalesced)
// ---------------------------------------------------------------------------
__global__ void __launch_bounds__(256, 2)
k_gemm2(const float* __restrict__ b2,
        const float* __restrict__ x,
        float* __restrict__ out) {
    __shared__ float sb2[128];
    const int tid = threadIdx.x;
    const int b = blockIdx.z;
    const int o20 = blockIdx.y * 128;
    const int s0 = blockIdx.x * 128;
    if (tid < 128) sb2[tid] = b2[o20 + tid];
    __syncthreads();

    const __half* Abase = g_W2h + (size_t)o20 * CO;
    const __half* Bbase = g_Hh + ((size_t)b * HW + s0) * CO;
    float acc[2][8][4];
    gemm_mainloop<CO / 32>(Abase, CO, Bbase, CO, acc, tid);

    const int lane = tid & 31, warp = tid >> 5;
    const int wm = warp & 3, wn = warp >> 2;
    const int g = lane >> 2, t = lane & 3;
#pragma unroll
    for (int mt = 0; mt < 2; mt++)
#pragma unroll
        for (int h = 0; h < 2; h++) {
            int mloc = wm * 32 + mt * 16 + h * 8 + g;
            int o2 = o20 + mloc;
            float bv = sb2[mloc];
            const float* xrow = x + (size_t)b * CC * HW + (size_t)o2 * HW + s0;
            float* orow = out + (size_t)b * CC * HW + (size_t)o2 * HW + s0;
#pragma unroll
            for (int nt = 0; nt < 8; nt++) {
                int sc = wn * 64 + nt * 8 + t * 2;
                float2 xr = *(const float2*)(xrow + sc);
                float2 ov;
                ov.x = acc[mt][nt][h * 2 + 0] + bv + xr.x;
                ov.y = acc[mt][nt][h * 2 + 1] + bv + xr.y;
                *(float2*)(orow + sc) = ov;
            }
        }
}

// ---------------------------------------------------------------------------
extern "C" void kernel_launch(void* const* d_in, const int* in_sizes, int n_in,
                              void* d_out, int out_size) {
    const float* x    = (const float*)d_in[0];
    const float* emb  = (const float*)d_in[1];
    const float* gn_w = (const float*)d_in[2];
    const float* gn_b = (const float*)d_in[3];
    const float* w1   = (const float*)d_in[4];
    const float* b1   = (const float*)d_in[5];
    const float* we   = (const float*)d_in[6];
    const float* be   = (const float*)d_in[7];
    const float* w2   = (const float*)d_in[8];
    const float* b2   = (const float*)d_in[9];
    float* out = (float*)d_out;

    static bool attr_set = false;
    if (!attr_set) {
        cudaFuncSetAttribute(k_gemm1, cudaFuncAttributeMaxDynamicSharedMemorySize, SMEM_BYTES);
        cudaFuncSetAttribute(k_gemm2, cudaFuncAttributeMaxDynamicSharedMemorySize, SMEM_BYTES);
        attr_set = true;
    }

    k_gnstats<<<BB * NG, 256>>>(x, gn_w, gn_b);
    k_emb<<<(2 * CO) / 8, 256>>>(emb, we, be);
    k_prep<<<(2 * CO * CC / 4) / 256, 256>>>(w1, w2);
    k_norm_t<<<dim3(HW / 64, CC / 64, BB), 256>>>(x);
    k_gemm1<<<dim3(HW / 128, CO / 128, BB), 256, SMEM_BYTES>>>(b1);
    k_gemm2<<<dim3(HW / 128, CC / 128, BB), 256, SMEM_BYTES>>>(b2, x, out);
}

// round 9
// speedup vs baseline: 1.0846x; 1.0466x over previous
#include <cuda_runtime.h>
#include <cuda_fp16.h>
#include <cstdint>

// Problem constants
#define BB   16
#define CC   384      // C
#define CO   1536     // EXP*C
#define HW   1024     // 32*32
#define EMB_ 1024
#define NG   32
#define CPG  12
#define EPS_ 1e-5f

// ---------------- scratch (device globals) ---------------------------------
__device__ __align__(16) float  g_A[BB * CC];
__device__ __align__(16) float  g_D[BB * CC];
__device__ __align__(16) float  g_S[BB * CO];
__device__ __align__(16) float  g_T[BB * CO];
__device__ __align__(16) __half g_W1h[CO * CC];                // fp16 w1 [o][c]
__device__ __align__(16) __half g_W2h[CC * CO];                // fp16 w2 [o2][c']
__device__ __align__(16) __half g_Xnh[(size_t)BB * HW * CC];   // fp16 xn^T [b][s][c]
__device__ __align__(16) __half g_Hh[(size_t)BB * HW * CO];    // fp16 hidden [b][s][o]

// ---------------- helpers --------------------------------------------------
__device__ __forceinline__ void cpa16(uint32_t dst, const void* src) {
    asm volatile("cp.async.cg.shared.global [%0], [%1], 16;" :: "r"(dst), "l"(src));
}
#define CP_COMMIT() asm volatile("cp.async.commit_group;")
#define CP_WAIT2()  asm volatile("cp.async.wait_group 2;")

#define LDSM4(r0, r1, r2, r3, a)                                               \
    asm volatile("ldmatrix.sync.aligned.m8n8.x4.shared.b16 {%0,%1,%2,%3}, [%4];" \
        : "=r"(r0), "=r"(r1), "=r"(r2), "=r"(r3) : "r"(a))

#define MMA_F16(d, a, b)                                                       \
    asm volatile(                                                              \
        "mma.sync.aligned.m16n8k16.row.col.f32.f16.f16.f32 "                   \
        "{%0,%1,%2,%3},{%4,%5,%6,%7},{%8,%9},{%0,%1,%2,%3};\n"                 \
        : "+f"((d)[0]), "+f"((d)[1]), "+f"((d)[2]), "+f"((d)[3])               \
        : "r"((a)[0]), "r"((a)[1]), "r"((a)[2]), "r"((a)[3]),                  \
          "r"((b)[0]), "r"((b)[1]))

// ---------------------------------------------------------------------------
// K1: GroupNorm stats -> per-channel affine (A, D)
// ---------------------------------------------------------------------------
__global__ void k_gnstats(const float* __restrict__ x,
                          const float* __restrict__ gnw,
                          const float* __restrict__ gnb) {
    int bg = blockIdx.x;
    int b = bg >> 5;
    int gi = bg & 31;
    const float4* p = (const float4*)(x + ((size_t)b * CC + (size_t)gi * CPG) * HW);
    float s = 0.f, ss = 0.f;
#pragma unroll
    for (int i = 0; i < 12; i++) {
        float4 v = p[threadIdx.x + i * 256];
        s  += v.x + v.y + v.z + v.w;
        ss += v.x * v.x + v.y * v.y + v.z * v.z + v.w * v.w;
    }
#pragma unroll
    for (int off = 16; off; off >>= 1) {
        s  += __shfl_xor_sync(0xffffffffu, s, off);
        ss += __shfl_xor_sync(0xffffffffu, ss, off);
    }
    __shared__ float sh[64];
    int w = threadIdx.x >> 5, l = threadIdx.x & 31;
    if (l == 0) { sh[w] = s; sh[32 + w] = ss; }
    __syncthreads();
    if (threadIdx.x < CPG) {
        float S = 0.f, SS = 0.f;
#pragma unroll
        for (int i = 0; i < 8; i++) { S += sh[i]; SS += sh[32 + i]; }
        float mean = S * (1.0f / 12288.0f);
        float var  = SS * (1.0f / 12288.0f) - mean * mean;
        float rstd = rsqrtf(var + EPS_);
        int cch = gi * CPG + threadIdx.x;
        float wv = gnw[cch], bv = gnb[cch];
        g_A[b * CC + cch] = rstd * wv;
        g_D[b * CC + cch] = bv - mean * rstd * wv;
    }
}

// ---------------------------------------------------------------------------
// K2: emb_out = emb @ we.T + be. One warp per output row o, weight row in
// registers, loop over all 16 batches (emb is L1-resident).
// ---------------------------------------------------------------------------
__global__ void k_emb(const float* __restrict__ emb,
                      const float* __restrict__ we,
                      const float* __restrict__ be) {
    int o = blockIdx.x * 8 + (threadIdx.x >> 5);   // 0..3071
    int lane = threadIdx.x & 31;
    const float4* w4 = (const float4*)(we + (size_t)o * EMB_);
    float4 wv[8];
#pragma unroll
    for (int i = 0; i < 8; i++) wv[i] = w4[lane + i * 32];
    float bev = be[o];

    float mine = 0.f;
#pragma unroll
    for (int b = 0; b < BB; b++) {
        const float4* e4 = (const float4*)(emb + (size_t)b * EMB_);
        float s = 0.f;
#pragma unroll
        for (int i = 0; i < 8; i++) {
            float4 ev = e4[lane + i * 32];
            s += ev.x * wv[i].x + ev.y * wv[i].y + ev.z * wv[i].z + ev.w * wv[i].w;
        }
#pragma unroll
        for (int off = 16; off; off >>= 1)
            s += __shfl_xor_sync(0xffffffffu, s, off);
        if (lane == b) mine = s;
    }
    if (lane < BB) {
        if (o < CO) g_S[lane * CO + o] = 1.0f + mine + bev;
        else        g_T[lane * CO + (o - CO)] = mine + bev;
    }
}

// ---------------------------------------------------------------------------
// K3: weights -> fp16
// ---------------------------------------------------------------------------
__global__ void k_prep(const float* __restrict__ w1,
                       const float* __restrict__ w2) {
    const int N1 = CO * CC / 4;
    int t = blockIdx.x * blockDim.x + threadIdx.x;
    const float4* src = (t < N1) ? (const float4*)w1 : (const float4*)w2;
    int i = (t < N1) ? t : t - N1;
    float4 v = src[i];
    __half2 lo = __floats2half2_rn(v.x, v.y);
    __half2 hi = __floats2half2_rn(v.z, v.w);
    uint2 pk = make_uint2(*(uint32_t*)&lo, *(uint32_t*)&hi);
    if (t < N1) ((uint2*)g_W1h)[i] = pk;
    else        ((uint2*)g_W2h)[i] = pk;
}

// ---------------------------------------------------------------------------
// K4: xn^T = fp16(A*x + D), transposed to [b][s][c]  (64x64 smem tiles)
// ---------------------------------------------------------------------------
__global__ void k_norm_t(const float* __restrict__ x) {
    __shared__ float sm[64][65];
    int b = blockIdx.z;
    int cg = blockIdx.y * 64;
    int sg = blockIdx.x * 64;
    int tid = threadIdx.x;
    int r = tid >> 2, q = tid & 3;
    float a = g_A[b * CC + cg + r];
    float d = g_D[b * CC + cg + r];
    const float* xr = x + ((size_t)b * CC + cg + r) * HW + sg + q * 16;
#pragma unroll
    for (int i = 0; i < 4; i++) {
        float4 v = *(const float4*)(xr + i * 4);
        sm[r][q * 16 + i * 4 + 0] = fmaf(a, v.x, d);
        sm[r][q * 16 + i * 4 + 1] = fmaf(a, v.y, d);
        sm[r][q * 16 + i * 4 + 2] = fmaf(a, v.z, d);
        sm[r][q * 16 + i * 4 + 3] = fmaf(a, v.w, d);
    }
    __syncthreads();
    __half* orow = g_Xnh + ((size_t)b * HW + sg + r) * CC + cg + q * 16;
#pragma unroll
    for (int i = 0; i < 4; i++) {
        __half2 lo = __floats2half2_rn(sm[q*16+i*4+0][r], sm[q*16+i*4+1][r]);
        __half2 hi = __floats2half2_rn(sm[q*16+i*4+2][r], sm[q*16+i*4+3][r]);
        *(uint2*)(orow + i * 4) = make_uint2(*(uint32_t*)&lo, *(uint32_t*)&hi);
    }
}

// ---------------------------------------------------------------------------
// GEMM core: CTA tile 128x128, BK=32 fp16, 4-stage cp.async.
// ONE barrier per k-tile, race-free ordering:
//   CP_WAIT2 -> __syncthreads -> fill(kt+3) -> commit -> compute(kt)
// RAW: each thread's wait (pending<=2 => stage kt landed) precedes the
//      barrier; barrier publishes all threads' copies of stage kt.
// WAR: fill targets stage (kt-1)&3, whose readers all finished compute(kt-1)
//      before this barrier.
// Depth: stages kt+1,kt+2 in flight at wait; fill kt+3 issued before compute
//      => 3 fills overlap compute.
// ---------------------------------------------------------------------------
#define ROWPITCH 80
#define TILE_B   (128 * ROWPITCH)      // 10240 B per operand tile
#define STG_B    (2 * TILE_B)          // 20480 B per stage
#define SMEM_BYTES (4 * STG_B)         // 81920 B

extern __shared__ uint8_t dsm8[];

__device__ __forceinline__ void fill_stage(uint32_t sdst,
        const __half* Asrc, size_t lda, const __half* Bsrc, size_t ldb, int tid) {
#pragma unroll
    for (int i = 0; i < 4; i++) {
        int ch = tid + i * 256;            // 0..1023
        int isB = ch >> 9;                 // 512 chunks per operand
        int r   = (ch & 511) >> 2;
        int cb  = ch & 3;
        const __half* src = isB ? (Bsrc + (size_t)r * ldb + cb * 8)
                                : (Asrc + (size_t)r * lda + cb * 8);
        cpa16(sdst + isB * TILE_B + r * ROWPITCH + cb * 16, src);
    }
}

template <int KT>
__device__ __forceinline__ void gemm_mainloop(
        const __half* Abase, size_t lda, const __half* Bbase, size_t ldb,
        float acc[2][8][4], int tid) {
    const int lane = tid & 31, warp = tid >> 5;
    const int wm = warp & 3, wn = warp >> 2;
#pragma unroll
    for (int i = 0; i < 2; i++)
#pragma unroll
        for (int j = 0; j < 8; j++)
#pragma unroll
            for (int e = 0; e < 4; e++) acc[i][j][e] = 0.f;

    uint32_t smb = (uint32_t)__cvta_generic_to_shared(dsm8);
    uint32_t aoff = (uint32_t)((wm * 32 + (lane & 15)) * ROWPITCH + (lane >> 4) * 16);
    uint32_t boff = (uint32_t)((wn * 64 + (lane & 7) + ((lane >> 4) << 3)) * ROWPITCH
                               + ((lane >> 3) & 1) * 16);

    // prologue: stages 0..2 (commits #1..#3)
#pragma unroll
    for (int s = 0; s < 3; s++) {
        fill_stage(smb + s * STG_B, Abase + s * 32, lda, Bbase + s * 32, ldb, tid);
        CP_COMMIT();
    }

    for (int kt = 0; kt < KT; kt++) {
        // commits before wait: 3 + kt; pending <= 2 => stage kt landed (this thread)
        CP_WAIT2();
        __syncthreads();   // publish stage kt; all readers of stage kt-1 done

        if (kt + 3 < KT)
            fill_stage(smb + ((kt + 3) & 3) * STG_B,
                       Abase + (size_t)(kt + 3) * 32, lda,
                       Bbase + (size_t)(kt + 3) * 32, ldb, tid);
        CP_COMMIT();       // commit every iter (empty ok) keeps the count exact

        uint32_t sA = smb + (kt & 3) * STG_B;
        uint32_t sB = sA + TILE_B;
#pragma unroll
        for (int kk = 0; kk < 2; kk++) {           // two k16 chunks
            uint32_t af[2][4], bf[8][2];
#pragma unroll
            for (int mt = 0; mt < 2; mt++)
                LDSM4(af[mt][0], af[mt][1], af[mt][2], af[mt][3],
                      sA + aoff + mt * 16 * ROWPITCH + kk * 32);
#pragma unroll
            for (int p = 0; p < 4; p++) {
                uint32_t r0, r1, r2, r3;
                LDSM4(r0, r1, r2, r3, sB + boff + p * 16 * ROWPITCH + kk * 32);
                bf[2 * p][0] = r0;  bf[2 * p][1] = r1;
                bf[2 * p + 1][0] = r2; bf[2 * p + 1][1] = r3;
            }
#pragma unroll
            for (int mt = 0; mt < 2; mt++)
#pragma unroll
                for (int nt = 0; nt < 8; nt++)
                    MMA_F16(acc[mt][nt], af[mt], bf[nt]);
        }
    }
}

// ---------------------------------------------------------------------------
// K5: GEMM1: D[s,o] = xn^T[s,c] @ w1[o,c]^T; M=s,N=o,K=CC.
// epilogue: +b1, silu, *(1+scale)+shift -> H[b][s][o] fp16
// ---------------------------------------------------------------------------
__global__ void __launch_bounds__(256, 2)
k_gemm1(const float* __restrict__ b1) {
    __shared__ float sb1[128], sS[128], sT[128];
    const int tid = threadIdx.x;
    const int b = blockIdx.z;
    const int o0 = blockIdx.y * 128;
    const int s0 = blockIdx.x * 128;
    if (tid < 128) {
        int o = o0 + tid;
        sb1[tid] = b1[o];
        sS[tid]  = g_S[b * CO + o];
        sT[tid]  = g_T[b * CO + o];
    }
    __syncthreads();

    const __half* Abase = g_Xnh + ((size_t)b * HW + s0) * CC;
    const __half* Bbase = g_W1h + (size_t)o0 * CC;
    float acc[2][8][4];
    gemm_mainloop<CC / 32>(Abase, CC, Bbase, CC, acc, tid);

    const int lane = tid & 31, warp = tid >> 5;
    const int wm = warp & 3, wn = warp >> 2;
    const int g = lane >> 2, t = lane & 3;
    __half* Hb = g_Hh + ((size_t)b * HW + s0) * CO + o0;
#pragma unroll
    for (int mt = 0; mt < 2; mt++)
#pragma unroll
        for (int h = 0; h < 2; h++) {
            int s_loc = wm * 32 + mt * 16 + h * 8 + g;
            __half* Hrow = Hb + (size_t)s_loc * CO;
#pragma unroll
            for (int nt = 0; nt < 8; nt++) {
                int oc = wn * 64 + nt * 8 + t * 2;
                float v0 = acc[mt][nt][h * 2 + 0] + sb1[oc];
                float v1 = acc[mt][nt][h * 2 + 1] + sb1[oc + 1];
                float h0 = v0 / (1.0f + __expf(-v0));
                float h1 = v1 / (1.0f + __expf(-v1));
                __half2 pk = __floats2half2_rn(h0 * sS[oc] + sT[oc],
                                               h1 * sS[oc + 1] + sT[oc + 1]);
                *(uint32_t*)(Hrow + oc) = *(uint32_t*)&pk;
            }
        }
}

// ---------------------------------------------------------------------------
// K6: GEMM2: D[o2,s] = w2[o2,c'] @ H[s,c']^T; M=o2,N=s,K=CO.
// epilogue: +b2 + residual x -> out[b][o2][s] (float2 coalesced)
// ---------------------------------------------------------------------------
__global__ void __launch_bounds__(256, 2)
k_gemm2(const float* __restrict__ b2,
        const float* __restrict__ x,
        float* __restrict__ out) {
    __shared__ float sb2[128];
    const int tid = threadIdx.x;
    const int b = blockIdx.z;
    const int o20 = blockIdx.y * 128;
    const int s0 = blockIdx.x * 128;
    if (tid < 128) sb2[tid] = b2[o20 + tid];
    __syncthreads();

    const __half* Abase = g_W2h + (size_t)o20 * CO;
    const __half* Bbase = g_Hh + ((size_t)b * HW + s0) * CO;
    float acc[2][8][4];
    gemm_mainloop<CO / 32>(Abase, CO, Bbase, CO, acc, tid);

    const int lane = tid & 31, warp = tid >> 5;
    const int wm = warp & 3, wn = warp >> 2;
    const int g = lane >> 2, t = lane & 3;
#pragma unroll
    for (int mt = 0; mt < 2; mt++)
#pragma unroll
        for (int h = 0; h < 2; h++) {
            int mloc = wm * 32 + mt * 16 + h * 8 + g;
            int o2 = o20 + mloc;
            float bv = sb2[mloc];
            const float* xrow = x + (size_t)b * CC * HW + (size_t)o2 * HW + s0;
            float* orow = out + (size_t)b * CC * HW + (size_t)o2 * HW + s0;
#pragma unroll
            for (int nt = 0; nt < 8; nt++) {
                int sc = wn * 64 + nt * 8 + t * 2;
                float2 xr = *(const float2*)(xrow + sc);
                float2 ov;
                ov.x = acc[mt][nt][h * 2 + 0] + bv + xr.x;
                ov.y = acc[mt][nt][h * 2 + 1] + bv + xr.y;
                *(float2*)(orow + sc) = ov;
            }
        }
}

// ---------------------------------------------------------------------------
extern "C" void kernel_launch(void* const* d_in, const int* in_sizes, int n_in,
                              void* d_out, int out_size) {
    const float* x    = (const float*)d_in[0];
    const float* emb  = (const float*)d_in[1];
    const float* gn_w = (const float*)d_in[2];
    const float* gn_b = (const float*)d_in[3];
    const float* w1   = (const float*)d_in[4];
    const float* b1   = (const float*)d_in[5];
    const float* we   = (const float*)d_in[6];
    const float* be   = (const float*)d_in[7];
    const float* w2   = (const float*)d_in[8];
    const float* b2   = (const float*)d_in[9];
    float* out = (float*)d_out;

    static bool attr_set = false;
    if (!attr_set) {
        cudaFuncSetAttribute(k_gemm1, cudaFuncAttributeMaxDynamicSharedMemorySize, SMEM_BYTES);
        cudaFuncSetAttribute(k_gemm2, cudaFuncAttributeMaxDynamicSharedMemorySize, SMEM_BYTES);
        attr_set = true;
    }

    k_gnstats<<<BB * NG, 256>>>(x, gn_w, gn_b);
    k_emb<<<(2 * CO) / 8, 256>>>(emb, we, be);
    k_prep<<<(2 * CO * CC / 4) / 256, 256>>>(w1, w2);
    k_norm_t<<<dim3(HW / 64, CC / 64, BB), 256>>>(x);
    k_gemm1<<<dim3(HW / 128, CO / 128, BB), 256, SMEM_BYTES>>>(b1);
    k_gemm2<<<dim3(HW / 128, CC / 128, BB), 256, SMEM_BYTES>>>(b2, x, out);
}

// round 11
// speedup vs baseline: 1.1025x; 1.0165x over previous
#include <cuda_runtime.h>
#include <cuda_fp16.h>
#include <cstdint>

// Problem constants
#define BB   16
#define CC   384      // C
#define CO   1536     // EXP*C
#define HW   1024     // 32*32
#define EMB_ 1024
#define NG   32
#define CPG  12
#define EPS_ 1e-5f

// ---------------- scratch (device globals) ---------------------------------
__device__ __align__(16) float  g_A[BB * CC];
__device__ __align__(16) float  g_D[BB * CC];
__device__ __align__(16) float  g_S[BB * CO];
__device__ __align__(16) float  g_T[BB * CO];
__device__ __align__(16) __half g_W1h[CO * CC];                // fp16 w1 [o][c]
__device__ __align__(16) __half g_W2h[CC * CO];                // fp16 w2 [o2][c']
__device__ __align__(16) __half g_Xnh[(size_t)BB * HW * CC];   // fp16 xn^T [b][s][c]
__device__ __align__(16) __half g_Hh[(size_t)BB * HW * CO];    // fp16 hidden [b][s][o]

// ---------------- helpers --------------------------------------------------
__device__ __forceinline__ void cpa16(uint32_t dst, const void* src) {
    asm volatile("cp.async.cg.shared.global [%0], [%1], 16;" :: "r"(dst), "l"(src));
}
#define CP_COMMIT() asm volatile("cp.async.commit_group;")
#define CP_WAITD()  asm volatile("cp.async.wait_group 3;")

#define LDSM4(r0, r1, r2, r3, a)                                               \
    asm volatile("ldmatrix.sync.aligned.m8n8.x4.shared.b16 {%0,%1,%2,%3}, [%4];" \
        : "=r"(r0), "=r"(r1), "=r"(r2), "=r"(r3) : "r"(a))

#define MMA_F16(d, a, b)                                                       \
    asm volatile(                                                              \
        "mma.sync.aligned.m16n8k16.row.col.f32.f16.f16.f32 "                   \
        "{%0,%1,%2,%3},{%4,%5,%6,%7},{%8,%9},{%0,%1,%2,%3};\n"                 \
        : "+f"((d)[0]), "+f"((d)[1]), "+f"((d)[2]), "+f"((d)[3])               \
        : "r"((a)[0]), "r"((a)[1]), "r"((a)[2]), "r"((a)[3]),                  \
          "r"((b)[0]), "r"((b)[1]))

// ---------------------------------------------------------------------------
// K_setup: FUSED gnstats + emb + w->fp16 prep, dispatched by blockIdx range.
//   blocks [0, 512):    GroupNorm stats -> (A, D)
//   blocks [512, 896):  emb_out = emb @ we.T + be -> S, T
//   blocks [896, 2048): w1/w2 -> fp16
// ---------------------------------------------------------------------------
__global__ void __launch_bounds__(256)
k_setup(const float* __restrict__ x,
        const float* __restrict__ gnw,
        const float* __restrict__ gnb,
        const float* __restrict__ emb,
        const float* __restrict__ we,
        const float* __restrict__ be,
        const float* __restrict__ w1,
        const float* __restrict__ w2) {
    int bid = blockIdx.x;
    if (bid < 512) {
        // ---- GroupNorm stats ----
        int b = bid >> 5;
        int gi = bid & 31;
        const float4* p = (const float4*)(x + ((size_t)b * CC + (size_t)gi * CPG) * HW);
        float s = 0.f, ss = 0.f;
#pragma unroll
        for (int i = 0; i < 12; i++) {
            float4 v = p[threadIdx.x + i * 256];
            s  += v.x + v.y + v.z + v.w;
            ss += v.x * v.x + v.y * v.y + v.z * v.z + v.w * v.w;
        }
#pragma unroll
        for (int off = 16; off; off >>= 1) {
            s  += __shfl_xor_sync(0xffffffffu, s, off);
            ss += __shfl_xor_sync(0xffffffffu, ss, off);
        }
        __shared__ float sh[64];
        int w = threadIdx.x >> 5, l = threadIdx.x & 31;
        if (l == 0) { sh[w] = s; sh[32 + w] = ss; }
        __syncthreads();
        if (threadIdx.x < CPG) {
            float S = 0.f, SS = 0.f;
#pragma unroll
            for (int i = 0; i < 8; i++) { S += sh[i]; SS += sh[32 + i]; }
            float mean = S * (1.0f / 12288.0f);
            float var  = SS * (1.0f / 12288.0f) - mean * mean;
            float rstd = rsqrtf(var + EPS_);
            int cch = gi * CPG + threadIdx.x;
            float wv = gnw[cch], bv = gnb[cch];
            g_A[b * CC + cch] = rstd * wv;
            g_D[b * CC + cch] = bv - mean * rstd * wv;
        }
    } else if (bid < 896) {
        // ---- emb GEMV: one warp per output row o, all 16 batches ----
        int o = (bid - 512) * 8 + (threadIdx.x >> 5);   // 0..3071
        int lane = threadIdx.x & 31;
        const float4* w4 = (const float4*)(we + (size_t)o * EMB_);
        float4 wv[8];
#pragma unroll
        for (int i = 0; i < 8; i++) wv[i] = w4[lane + i * 32];
        float bev = be[o];

        float mine = 0.f;
#pragma unroll
        for (int b = 0; b < BB; b++) {
            const float4* e4 = (const float4*)(emb + (size_t)b * EMB_);
            float s = 0.f;
#pragma unroll
            for (int i = 0; i < 8; i++) {
                float4 ev = e4[lane + i * 32];
                s += ev.x * wv[i].x + ev.y * wv[i].y + ev.z * wv[i].z + ev.w * wv[i].w;
            }
#pragma unroll
            for (int off = 16; off; off >>= 1)
                s += __shfl_xor_sync(0xffffffffu, s, off);
            if (lane == b) mine = s;
        }
        if (lane < BB) {
            if (o < CO) g_S[lane * CO + o] = 1.0f + mine + bev;
            else        g_T[lane * CO + (o - CO)] = mine + bev;
        }
    } else {
        // ---- weights -> fp16 ----
        const int N1 = CO * CC / 4;
        int t = (bid - 896) * 256 + threadIdx.x;
        const float4* src = (t < N1) ? (const float4*)w1 : (const float4*)w2;
        int i = (t < N1) ? t : t - N1;
        float4 v = src[i];
        __half2 lo = __floats2half2_rn(v.x, v.y);
        __half2 hi = __floats2half2_rn(v.z, v.w);
        uint2 pk = make_uint2(*(uint32_t*)&lo, *(uint32_t*)&hi);
        if (t < N1) ((uint2*)g_W1h)[i] = pk;
        else        ((uint2*)g_W2h)[i] = pk;
    }
}

// ---------------------------------------------------------------------------
// K_norm_t: xn^T = fp16(A*x + D), transposed to [b][s][c]  (64x64 smem tiles)
// ---------------------------------------------------------------------------
__global__ void k_norm_t(const float* __restrict__ x) {
    __shared__ float sm[64][65];
    int b = blockIdx.z;
    int cg = blockIdx.y * 64;
    int sg = blockIdx.x * 64;
    int tid = threadIdx.x;
    int r = tid >> 2, q = tid & 3;
    float a = g_A[b * CC + cg + r];
    float d = g_D[b * CC + cg + r];
    const float* xr = x + ((size_t)b * CC + cg + r) * HW + sg + q * 16;
#pragma unroll
    for (int i = 0; i < 4; i++) {
        float4 v = *(const float4*)(xr + i * 4);
        sm[r][q * 16 + i * 4 + 0] = fmaf(a, v.x, d);
        sm[r][q * 16 + i * 4 + 1] = fmaf(a, v.y, d);
        sm[r][q * 16 + i * 4 + 2] = fmaf(a, v.z, d);
        sm[r][q * 16 + i * 4 + 3] = fmaf(a, v.w, d);
    }
    __syncthreads();
    __half* orow = g_Xnh + ((size_t)b * HW + sg + r) * CC + cg + q * 16;
#pragma unroll
    for (int i = 0; i < 4; i++) {
        __half2 lo = __floats2half2_rn(sm[q*16+i*4+0][r], sm[q*16+i*4+1][r]);
        __half2 hi = __floats2half2_rn(sm[q*16+i*4+2][r], sm[q*16+i*4+3][r]);
        *(uint2*)(orow + i * 4) = make_uint2(*(uint32_t*)&lo, *(uint32_t*)&hi);
    }
}

// ---------------------------------------------------------------------------
// GEMM core: CTA tile 128x128, BK=32 fp16, FIVE-stage cp.async ring.
// One barrier per k-tile, race-free ordering:
//   CP_WAITD(wait_group 3) -> __syncthreads -> fill((kt+4)%5) -> commit
//   -> compute(kt%5)
// RAW: commits before wait = 4+kt; pending<=3 => stage kt landed (thread),
//      barrier publishes it block-wide.
// WAR: fill target (kt+4)%5 == (kt-1)%5; its readers finished compute(kt-1)
//      before this barrier.
// Depth: stages kt+1..kt+3 in flight at the wait, +fill kt+4 => 4 overlapped.
// ---------------------------------------------------------------------------
#define ROWPITCH 80
#define TILE_B   (128 * ROWPITCH)      // 10240 B per operand tile
#define STG_B    (2 * TILE_B)          // 20480 B per stage
#define NSTAGE   5
#define SMEM_BYTES (NSTAGE * STG_B)    // 102400 B

extern __shared__ uint8_t dsm8[];

__device__ __forceinline__ void fill_stage(uint32_t sdst,
        const __half* Asrc, size_t lda, const __half* Bsrc, size_t ldb, int tid) {
#pragma unroll
    for (int i = 0; i < 4; i++) {
        int ch = tid + i * 256;            // 0..1023
        int isB = ch >> 9;                 // 512 chunks per operand
        int r   = (ch & 511) >> 2;
        int cb  = ch & 3;
        const __half* src = isB ? (Bsrc + (size_t)r * ldb + cb * 8)
                                : (Asrc + (size_t)r * lda + cb * 8);
        cpa16(sdst + isB * TILE_B + r * ROWPITCH + cb * 16, src);
    }
}

template <int KT>
__device__ __forceinline__ void gemm_mainloop(
        const __half* Abase, size_t lda, const __half* Bbase, size_t ldb,
        float acc[2][8][4], int tid) {
    const int lane = tid & 31, warp = tid >> 5;
    const int wm = warp & 3, wn = warp >> 2;
#pragma unroll
    for (int i = 0; i < 2; i++)
#pragma unroll
        for (int j = 0; j < 8; j++)
#pragma unroll
            for (int e = 0; e < 4; e++) acc[i][j][e] = 0.f;

    uint32_t smb = (uint32_t)__cvta_generic_to_shared(dsm8);
    uint32_t aoff = (uint32_t)((wm * 32 + (lane & 15)) * ROWPITCH + (lane >> 4) * 16);
    uint32_t boff = (uint32_t)((wn * 64 + (lane & 7) + ((lane >> 4) << 3)) * ROWPITCH
                               + ((lane >> 3) & 1) * 16);

    // prologue: stages 0..3 (commits #1..#4)
#pragma unroll
    for (int s = 0; s < NSTAGE - 1; s++) {
        fill_stage(smb + s * STG_B, Abase + s * 32, lda, Bbase + s * 32, ldb, tid);
        CP_COMMIT();
    }

    int s_cur = 0;                 // ring index of stage kt
    int s_fill = NSTAGE - 1;       // ring index of stage kt+4
    for (int kt = 0; kt < KT; kt++) {
        // commits before wait: 4 + kt; pending <= 3 => stage kt landed (thread)
        CP_WAITD();
        __syncthreads();   // publish stage kt; readers of stage kt-1 all done

        if (kt + NSTAGE - 1 < KT)
            fill_stage(smb + s_fill * STG_B,
                       Abase + (size_t)(kt + NSTAGE - 1) * 32, lda,
                       Bbase + (size_t)(kt + NSTAGE - 1) * 32, ldb, tid);
        CP_COMMIT();       // commit every iter (empty ok) keeps the count exact

        uint32_t sA = smb + s_cur * STG_B;
        uint32_t sB = sA + TILE_B;
#pragma unroll
        for (int kk = 0; kk < 2; kk++) {           // two k16 chunks
            uint32_t af[2][4], bf[8][2];
#pragma unroll
            for (int mt = 0; mt < 2; mt++)
                LDSM4(af[mt][0], af[mt][1], af[mt][2], af[mt][3],
                      sA + aoff + mt * 16 * ROWPITCH + kk * 32);
#pragma unroll
            for (int p = 0; p < 4; p++) {
                uint32_t r0, r1, r2, r3;
                LDSM4(r0, r1, r2, r3, sB + boff + p * 16 * ROWPITCH + kk * 32);
                bf[2 * p][0] = r0;  bf[2 * p][1] = r1;
                bf[2 * p + 1][0] = r2; bf[2 * p + 1][1] = r3;
            }
#pragma unroll
            for (int mt = 0; mt < 2; mt++)
#pragma unroll
                for (int nt = 0; nt < 8; nt++)
                    MMA_F16(acc[mt][nt], af[mt], bf[nt]);
        }
        s_cur  = (s_cur  == NSTAGE - 1) ? 0 : s_cur + 1;
        s_fill = (s_fill == NSTAGE - 1) ? 0 : s_fill + 1;
    }
}

// ---------------------------------------------------------------------------
// K_gemm1: D[s,o] = xn^T[s,c] @ w1[o,c]^T; M=s,N=o,K=CC.
// epilogue: +b1, silu, *(1+scale)+shift -> H[b][s][o] fp16
// ---------------------------------------------------------------------------
__global__ void __launch_bounds__(256, 2)
k_gemm1(const float* __restrict__ b1) {
    __shared__ float sb1[128], sS[128], sT[128];
    const int tid = threadIdx.x;
    const int b = blockIdx.z;
    const int o0 = blockIdx.y * 128;
    const int s0 = blockIdx.x * 128;
    if (tid < 128) {
        int o = o0 + tid;
        sb1[tid] = b1[o];
        sS[tid]  = g_S[b * CO + o];
        sT[tid]  = g_T[b * CO + o];
    }
    __syncthreads();

    const __half* Abase = g_Xnh + ((size_t)b * HW + s0) * CC;
    const __half* Bbase = g_W1h + (size_t)o0 * CC;
    float acc[2][8][4];
    gemm_mainloop<CC / 32>(Abase, CC, Bbase, CC, acc, tid);

    const int lane = tid & 31, warp = tid >> 5;
    const int wm = warp & 3, wn = warp >> 2;
    const int g = lane >> 2, t = lane & 3;
    __half* Hb = g_Hh + ((size_t)b * HW + s0) * CO + o0;
#pragma unroll
    for (int mt = 0; mt < 2; mt++)
#pragma unroll
        for (int h = 0; h < 2; h++) {
            int s_loc = wm * 32 + mt * 16 + h * 8 + g;
            __half* Hrow = Hb + (size_t)s_loc * CO;
#pragma unroll
            for (int nt = 0; nt < 8; nt++) {
                int oc = wn * 64 + nt * 8 + t * 2;
                float v0 = acc[mt][nt][h * 2 + 0] + sb1[oc];
                float v1 = acc[mt][nt][h * 2 + 1] + sb1[oc + 1];
                float h0 = v0 / (1.0f + __expf(-v0));
                float h1 = v1 / (1.0f + __expf(-v1));
                __half2 pk = __floats2half2_rn(h0 * sS[oc] + sT[oc],
                                               h1 * sS[oc + 1] + sT[oc + 1]);
                *(uint32_t*)(Hrow + oc) = *(uint32_t*)&pk;
            }
        }
}

// ---------------------------------------------------------------------------
// K_gemm2: D[o2,s] = w2[o2,c'] @ H[s,c']^T; M=o2,N=s,K=CO.  (128x128 tiles —
// measured best; 64-wide s-tiles were +18.7us, do not revisit.)
// epilogue: +b2 + residual x -> out[b][o2][s] (float2 coalesced)
// ---------------------------------------------------------------------------
__global__ void __launch_bounds__(256, 2)
k_gemm2(const float* __restrict__ b2,
        const float* __restrict__ x,
        float* __restrict__ out) {
    __shared__ float sb2[128];
    const int tid = threadIdx.x;
    const int b = blockIdx.z;
    const int o20 = blockIdx.y * 128;
    const int s0 = blockIdx.x * 128;
    if (tid < 128) sb2[tid] = b2[o20 + tid];
    __syncthreads();

    const __half* Abase = g_W2h + (size_t)o20 * CO;
    const __half* Bbase = g_Hh + ((size_t)b * HW + s0) * CO;
    float acc[2][8][4];
    gemm_mainloop<CO / 32>(Abase, CO, Bbase, CO, acc, tid);

    const int lane = tid & 31, warp = tid >> 5;
    const int wm = warp & 3, wn = warp >> 2;
    const int g = lane >> 2, t = lane & 3;
#pragma unroll
    for (int mt = 0; mt < 2; mt++)
#pragma unroll
        for (int h = 0; h < 2; h++) {
            int mloc = wm * 32 + mt * 16 + h * 8 + g;
            int o2 = o20 + mloc;
            float bv = sb2[mloc];
            const float* xrow = x + (size_t)b * CC * HW + (size_t)o2 * HW + s0;
            float* orow = out + (size_t)b * CC * HW + (size_t)o2 * HW + s0;
#pragma unroll
            for (int nt = 0; nt < 8; nt++) {
                int sc = wn * 64 + nt * 8 + t * 2;
                float2 xr = *(const float2*)(xrow + sc);
                float2 ov;
                ov.x = acc[mt][nt][h * 2 + 0] + bv + xr.x;
                ov.y = acc[mt][nt][h * 2 + 1] + bv + xr.y;
                *(float2*)(orow + sc) = ov;
            }
        }
}

// ---------------------------------------------------------------------------
extern "C" void kernel_launch(void* const* d_in, const int* in_sizes, int n_in,
                              void* d_out, int out_size) {
    const float* x    = (const float*)d_in[0];
    const float* emb  = (const float*)d_in[1];
    const float* gn_w = (const float*)d_in[2];
    const float* gn_b = (const float*)d_in[3];
    const float* w1   = (const float*)d_in[4];
    const float* b1   = (const float*)d_in[5];
    const float* we   = (const float*)d_in[6];
    const float* be   = (const float*)d_in[7];
    const float* w2   = (const float*)d_in[8];
    const float* b2   = (const float*)d_in[9];
    float* out = (float*)d_out;

    static bool attr_set = false;
    if (!attr_set) {
        cudaFuncSetAttribute(k_gemm1, cudaFuncAttributeMaxDynamicSharedMemorySize, SMEM_BYTES);
        cudaFuncSetAttribute(k_gemm2, cudaFuncAttributeMaxDynamicSharedMemorySize, SMEM_BYTES);
        attr_set = true;
    }

    // setup: 512 gnstats blocks + 384 emb blocks + 1152 prep blocks
    k_setup<<<2048, 256>>>(x, gn_w, gn_b, emb, we, be, w1, w2);
    k_norm_t<<<dim3(HW / 64, CC / 64, BB), 256>>>(x);
    k_gemm1<<<dim3(HW / 128, CO / 128, BB), 256, SMEM_BYTES>>>(b1);
    k_gemm2<<<dim3(HW / 128, CC / 128, BB), 256, SMEM_BYTES>>>(b2, x, out);
}